// round 12
// baseline (speedup 1.0000x reference)
#include <cuda_runtime.h>
#include <math.h>

#define NBODY 512
#define NVERT 6890
#define NJ 24
#define NCOL (NVERT*3)
#define KP 224               /* 207 pose + 10 beta + 1 template + 6 zero pad */
#define NTILE 216
#define NCOLPAD (NTILE*96)   /* 20736, col = v*3+c */
#define BN 64
#define BV 32

typedef unsigned long long ull;

// Scratch (device globals — no allocation anywhere)
__device__ float d_PextT[(size_t)KP * NCOLPAD]; // [k][col], col = v*3+c
__device__ float d_LextT[KP * NBODY];           // [k][body]
__device__ float2 d_Gm2[(NBODY/2) * NJ * 12];   // body-pair interleaved
__device__ float d_JS[NJ * 3 * 10];
__device__ float d_Jt[NJ * 3];

__constant__ int c_par[NJ] = {0,0,0,0,1,2,3,4,5,6,7,8,9,9,9,12,13,14,16,17,18,19,20,21};

// ---- packed f32x2 helpers -------------------------------------------------
__device__ __forceinline__ ull ffma2(ull a, ull b, ull c) {
    ull d;
    asm("fma.rn.f32x2 %0, %1, %2, %3;" : "=l"(d) : "l"(a), "l"(b), "l"(c));
    return d;
}
__device__ __forceinline__ ull dup2(float x) {
    ull d; unsigned u = __float_as_uint(x);
    asm("mov.b64 %0, {%1, %1};" : "=l"(d) : "r"(u));
    return d;
}
__device__ __forceinline__ float2 unpack2(ull p) {
    float2 r;
    asm("mov.b64 {%0, %1}, %2;" : "=f"(r.x), "=f"(r.y) : "l"(p));
    return r;
}
// ---- cp.async helpers ------------------------------------------------------
__device__ __forceinline__ void cp_async16(unsigned s, const void* g) {
    asm volatile("cp.async.cg.shared.global [%0], [%1], 16;\n" :: "r"(s), "l"(g));
}
__device__ __forceinline__ void cp_commit() {
    asm volatile("cp.async.commit_group;\n");
}
template<int N> __device__ __forceinline__ void cp_wait() {
    asm volatile("cp.async.wait_group %0;\n" :: "n"(N));
}

// ---------------------------------------------------------------------------
// Kernel 1: fold J_regressor into shape space. 72 blocks = (joint, coord).
// ---------------------------------------------------------------------------
__global__ void __launch_bounds__(256)
jreg_kernel(const float* __restrict__ Jreg,
            const float* __restrict__ shapedirs,
            const float* __restrict__ v_template)
{
    int j = blockIdx.x / 3, c = blockIdx.x - j * 3;
    int tid = threadIdx.x;
    float acc[11];
#pragma unroll
    for (int q = 0; q < 11; q++) acc[q] = 0.f;
    for (int v = tid; v < NVERT; v += 256) {
        float jr = Jreg[j * NVERT + v];
        acc[0] += jr * v_template[v * 3 + c];
#pragma unroll
        for (int b = 0; b < 10; b++)
            acc[1 + b] += jr * shapedirs[(v * 3 + c) * 10 + b];
    }
    __shared__ float red[8][11];
    int lane = tid & 31, wid = tid >> 5;
#pragma unroll
    for (int q = 0; q < 11; q++) {
        float s = acc[q];
        for (int o = 16; o; o >>= 1) s += __shfl_down_sync(0xffffffffu, s, o);
        if (lane == 0) red[wid][q] = s;
    }
    __syncthreads();
    if (tid < 11) {
        int q = tid;
        float s = 0.f;
        for (int w = 0; w < 8; w++) s += red[w][q];
        if (q == 0) d_Jt[j * 3 + c] = s;
        else        d_JS[(j * 3 + c) * 10 + (q - 1)] = s;
    }
}

// ---------------------------------------------------------------------------
// Kernel 2: fused transpose + per-body prep. Grid 712:
//  blocks [0,648): transpose one 32-col strip over full K=224 (R8 version).
//  blocks [648,712): body prep, 8 warps/block, 1 warp/body (needs d_Jt/d_JS).
// Smem unioned in one byte array (29.3KB transpose vs 18.3KB body).
// blockDim = (32,8).
// ---------------------------------------------------------------------------
__global__ void __launch_bounds__(256)
prep_body_kernel(const float* __restrict__ posedirs,
                 const float* __restrict__ shapedirs,
                 const float* __restrict__ v_template,
                 const float* __restrict__ beta,
                 const float* __restrict__ pose)
{
    __shared__ __align__(16) float sm[32 * 229];   // 29312 B

    int bid = blockIdx.x;
    int tx = threadIdx.x, ty = threadIdx.y;

    if (bid < 648) {
        // ---- transpose strip (exact R8 logic) ----
        float (*tile)[229] = (float (*)[229])sm;
        int rbase = bid * 32;
        float r[28];
#pragma unroll
        for (int q = 0; q < 28; q++) {
            int kk0 = (q >> 2) * 32;
            int i = q & 3;
            int row = rbase + ty * 4 + i;
            int k = kk0 + tx;
            float v = 0.f;
            if (row < NCOL) {
                if (k < 207)       v = posedirs[row * 207 + k];
                else if (k < 217)  v = shapedirs[row * 10 + (k - 207)];
                else if (k == 217) v = v_template[row];
            }
            r[q] = v;
        }
#pragma unroll
        for (int q = 0; q < 28; q++) {
            int kk0 = (q >> 2) * 32;
            int i = q & 3;
            tile[ty * 4 + i][kk0 + tx] = r[q];
        }
        __syncthreads();
#pragma unroll
        for (int q = 0; q < 28; q++) {
            int k = q * 8 + ty;
            d_PextT[(size_t)k * NCOLPAD + rbase + tx] = tile[tx][k];
        }
    } else {
        // ---- per-body prep: Rodrigues, LextT, joints, chain, G' ----
        int w = ty;               // warp index 0..7
        int lane = tx;
        int n = (bid - 648) * 8 + w;

        float* sR = sm;                      // [8][24][9]  offset 0
        float* sJ = sm + 1728;               // [8][24][3]
        float* sG = sm + 2304;               // [8][24][12]
        float* sBeta = sm + 4608;            // [8][10]
#define SR(w,j,e) sR[(w) * 216 + (j) * 9 + (e)]
#define SJ(w,j,c) sJ[(w) * 72 + (j) * 3 + (c)]
#define SG(w,j,e) sG[(w) * 288 + (j) * 12 + (e)]

        if (lane < 10) sBeta[w * 10 + lane] = beta[n * 10 + lane];
        if (lane < NJ) {
            float x = pose[n * 72 + lane * 3 + 0];
            float y = pose[n * 72 + lane * 3 + 1];
            float z = pose[n * 72 + lane * 3 + 2];
            float th = sqrtf(x * x + y * y + z * z) + 1e-8f;
            float inv = 1.0f / th;
            x *= inv; y *= inv; z *= inv;
            float s, c;
            sincosf(th, &s, &c);
            float C = 1.0f - c;
            SR(w, lane, 0) = c + C * x * x;     SR(w, lane, 1) = C * x * y - s * z; SR(w, lane, 2) = C * x * z + s * y;
            SR(w, lane, 3) = C * x * y + s * z; SR(w, lane, 4) = c + C * y * y;     SR(w, lane, 5) = C * y * z - s * x;
            SR(w, lane, 6) = C * x * z - s * y; SR(w, lane, 7) = C * y * z + s * x; SR(w, lane, 8) = c + C * z * z;
        }
        __syncwarp();

        for (int t = lane; t < 207; t += 32) {
            int jj = 1 + t / 9, e = t - (t / 9) * 9;
            d_LextT[t * NBODY + n] = SR(w, jj, e) - ((e == 0 || e == 4 || e == 8) ? 1.0f : 0.0f);
        }
        for (int t = lane; t < 17; t += 32) {
            int k = 207 + t;
            d_LextT[k * NBODY + n] = (t < 10) ? sBeta[w * 10 + t] : ((k == 217) ? 1.0f : 0.0f);
        }

        for (int t = lane; t < 72; t += 32) {
            int jj = t / 3, c = t - jj * 3;
            float s = d_Jt[jj * 3 + c];
#pragma unroll
            for (int b = 0; b < 10; b++) s += d_JS[(jj * 3 + c) * 10 + b] * sBeta[w * 10 + b];
            SJ(w, jj, c) = s;
        }
        __syncwarp();

        if (lane < 12) {
            int r = lane >> 2, cc = lane & 3;
            SG(w, 0, lane) = (cc < 3) ? SR(w, 0, r * 3 + cc) : SJ(w, 0, r);
        }
        __syncwarp();
        for (int i = 1; i < NJ; i++) {
            int p = c_par[i];
            float val = 0.f;
            if (lane < 12) {
                int r = lane >> 2, cc = lane & 3;
                float t0, t1, t2;
                if (cc < 3) { t0 = SR(w, i, cc); t1 = SR(w, i, 3 + cc); t2 = SR(w, i, 6 + cc); }
                else { t0 = SJ(w, i, 0) - SJ(w, p, 0); t1 = SJ(w, i, 1) - SJ(w, p, 1); t2 = SJ(w, i, 2) - SJ(w, p, 2); }
                val = SG(w, p, r * 4 + 0) * t0 + SG(w, p, r * 4 + 1) * t1 + SG(w, p, r * 4 + 2) * t2;
                if (cc == 3) val += SG(w, p, r * 4 + 3);
            }
            __syncwarp();
            if (lane < 12) SG(w, i, lane) = val;
            __syncwarp();
        }

        for (int t = lane; t < 72; t += 32) {
            int jj = t / 3, r = t - jj * 3;
            float rj = SG(w, jj, r * 4 + 0) * SJ(w, jj, 0) + SG(w, jj, r * 4 + 1) * SJ(w, jj, 1)
                     + SG(w, jj, r * 4 + 2) * SJ(w, jj, 2);
            SG(w, jj, r * 4 + 3) -= rj;
        }
        __syncwarp();
        for (int t = lane; t < NJ * 12; t += 32) {
            float g = SG(w, t / 12, t - (t / 12) * 12);
            if (n & 1) d_Gm2[(n >> 1) * (NJ * 12) + t].y = g;
            else       d_Gm2[(n >> 1) * (NJ * 12) + t].x = g;
        }
#undef SR
#undef SJ
#undef SG
    }
}

// ---------------------------------------------------------------------------
// Main fused kernel — EXACT R8 shape (best passing: 179.3us total).
// 128 thr = 16 tx x 8 ty. Tile 64 bodies x 32 verts.
// ---------------------------------------------------------------------------
#define AS_OFF(buf, kk, c) ((buf) * 2048 + (kk) * 64 + (c))
#define BS_OFF(buf, kk, c) (4096 + (buf) * 3200 + (kk) * 100 + (c))
#define GS_STRIDE 74
#define GBUF_F2 2368
#define WS_OFF 9472

__global__ void __launch_bounds__(128, 4)
smpl_main_kernel(const float* __restrict__ weights, float* __restrict__ out)
{
    __shared__ __align__(16) float smemf[10496];   // 42 KB

    float2* Gs2 = (float2*)smemf;
    float* Ws = smemf + WS_OFF;

    int tid = threadIdx.x;
    int tx = tid & 15, ty = tid >> 4;
    int nBase = blockIdx.y * BN;
    int vBase = blockIdx.x * BV;
    int colBase = blockIdx.x * 96;
    int pBase = nBase >> 1;

    unsigned smem_base = (unsigned)__cvta_generic_to_shared(smemf);

    ull vp2[4][6];
#pragma unroll
    for (int p = 0; p < 4; p++)
#pragma unroll
        for (int j = 0; j < 6; j++) vp2[p][j] = 0ull;

    {
#pragma unroll
        for (int t = 0; t < 4; t++) {
            int idx = tid + t * 128;
            int kk = idx >> 4, c4 = idx & 15;
            cp_async16(smem_base + AS_OFF(0, kk, c4 * 4) * 4,
                       &d_LextT[kk * NBODY + nBase + c4 * 4]);
        }
#pragma unroll
        for (int t = 0; t < 6; t++) {
            int idx = tid + t * 128;
            int kk = idx / 24, c4 = idx - kk * 24;
            cp_async16(smem_base + BS_OFF(0, kk, c4 * 4) * 4,
                       &d_PextT[(size_t)kk * NCOLPAD + colBase + c4 * 4]);
        }
        cp_commit();
    }

    for (int tt = 0; tt < 7; tt++) {
        int cur = tt & 1;
        if (tt < 6) {
            int nb = cur ^ 1;
            int k1 = (tt + 1) * 32;
#pragma unroll
            for (int t = 0; t < 4; t++) {
                int idx = tid + t * 128;
                int kk = idx >> 4, c4 = idx & 15;
                cp_async16(smem_base + AS_OFF(nb, kk, c4 * 4) * 4,
                           &d_LextT[(k1 + kk) * NBODY + nBase + c4 * 4]);
            }
#pragma unroll
            for (int t = 0; t < 6; t++) {
                int idx = tid + t * 128;
                int kk = idx / 24, c4 = idx - kk * 24;
                cp_async16(smem_base + BS_OFF(nb, kk, c4 * 4) * 4,
                           &d_PextT[(size_t)(k1 + kk) * NCOLPAD + colBase + c4 * 4]);
            }
            cp_commit();
            cp_wait<1>();
        } else {
            cp_wait<0>();
        }
        __syncthreads();

#pragma unroll
        for (int kk = 0; kk < 32; kk++) {
            ulonglong2 A0 = *(const ulonglong2*)&smemf[AS_OFF(cur, kk, ty * 8)];
            ulonglong2 A1 = *(const ulonglong2*)&smemf[AS_OFF(cur, kk, ty * 8 + 4)];
            float2 b01 = *(const float2*)&smemf[BS_OFF(cur, kk, tx * 6)];
            float2 b23 = *(const float2*)&smemf[BS_OFF(cur, kk, tx * 6 + 2)];
            float2 b45 = *(const float2*)&smemf[BS_OFF(cur, kk, tx * 6 + 4)];
            ull bd[6];
            bd[0] = dup2(b01.x); bd[1] = dup2(b01.y);
            bd[2] = dup2(b23.x); bd[3] = dup2(b23.y);
            bd[4] = dup2(b45.x); bd[5] = dup2(b45.y);
#pragma unroll
            for (int j = 0; j < 6; j++) {
                vp2[0][j] = ffma2(A0.x, bd[j], vp2[0][j]);
                vp2[1][j] = ffma2(A0.y, bd[j], vp2[1][j]);
                vp2[2][j] = ffma2(A1.x, bd[j], vp2[2][j]);
                vp2[3][j] = ffma2(A1.y, bd[j], vp2[3][j]);
            }
        }
        __syncthreads();
    }

    // ---- Phase 2 prologue: prefetch G chunk 0, load Ws ----
    {
#pragma unroll
        for (int i = 0; i < 9; i++) {
            int t = tid + i * 128;
            int pl = t / 36, seg = t - pl * 36;
            cp_async16(smem_base + (pl * GS_STRIDE + seg * 2) * 8,
                       &d_Gm2[(pBase + pl) * (NJ * 12) + seg * 2]);
        }
        cp_commit();
    }
    for (int t = tid; t < BV * 24; t += 128) {
        int vl = t / 24, j2 = t - vl * 24;
        int v = vBase + vl;
        Ws[vl * 25 + j2] = (v < NVERT) ? weights[v * 24 + j2] : 0.f;
    }

    ull o2[4][6];
#pragma unroll
    for (int p = 0; p < 4; p++)
#pragma unroll
        for (int j = 0; j < 6; j++) o2[p][j] = 0ull;

    for (int jc = 0; jc < 4; jc++) {
        int cur = jc & 1;
        if (jc < 3) {
            int nb = cur ^ 1;
#pragma unroll
            for (int i = 0; i < 9; i++) {
                int t = tid + i * 128;
                int pl = t / 36, seg = t - pl * 36;
                cp_async16(smem_base + (nb * GBUF_F2 + pl * GS_STRIDE + seg * 2) * 8,
                           &d_Gm2[(pBase + pl) * (NJ * 12) + (jc + 1) * 72 + seg * 2]);
            }
            cp_commit();
            cp_wait<1>();
        } else {
            cp_wait<0>();
        }
        __syncthreads();
#pragma unroll
        for (int jj = 0; jj < 6; jj++) {
            ull w0 = dup2(Ws[(tx * 2) * 25 + jc * 6 + jj]);
            ull w1 = dup2(Ws[(tx * 2 + 1) * 25 + jc * 6 + jj]);
#pragma unroll
            for (int q = 0; q < 4; q++) {
                const ull* g = (const ull*)&Gs2[cur * GBUF_F2 + (ty * 4 + q) * GS_STRIDE + jj * 12];
#pragma unroll
                for (int c = 0; c < 3; c++) {
                    ull g0 = g[c * 4 + 0], g1 = g[c * 4 + 1];
                    ull g2 = g[c * 4 + 2], g3 = g[c * 4 + 3];
                    ull t0 = ffma2(g0, vp2[q][0], ffma2(g1, vp2[q][1], ffma2(g2, vp2[q][2], g3)));
                    o2[q][c] = ffma2(w0, t0, o2[q][c]);
                    ull t1 = ffma2(g0, vp2[q][3], ffma2(g1, vp2[q][4], ffma2(g2, vp2[q][5], g3)));
                    o2[q][3 + c] = ffma2(w1, t1, o2[q][3 + c]);
                }
            }
        }
        __syncthreads();
    }

    // ---- Store ----
#pragma unroll
    for (int q = 0; q < 4; q++) {
        int n0 = nBase + ty * 8 + 2 * q;
#pragma unroll
        for (int vv = 0; vv < 2; vv++) {
            int v = vBase + tx * 2 + vv;
            if (v < NVERT) {
                size_t b0 = ((size_t)n0 * NVERT + v) * 3;
                size_t b1 = ((size_t)(n0 + 1) * NVERT + v) * 3;
#pragma unroll
                for (int c = 0; c < 3; c++) {
                    float2 pr = unpack2(o2[q][vv * 3 + c]);
                    out[b0 + c] = pr.x;
                    out[b1 + c] = pr.y;
                }
            }
        }
    }
}

// ---------------------------------------------------------------------------
extern "C" void kernel_launch(void* const* d_in, const int* in_sizes, int n_in,
                              void* d_out, int out_size)
{
    const float* beta        = (const float*)d_in[0];
    const float* pose        = (const float*)d_in[1];
    const float* v_template  = (const float*)d_in[2];
    const float* shapedirs   = (const float*)d_in[3];
    const float* posedirs    = (const float*)d_in[4];
    const float* J_regressor = (const float*)d_in[5];
    const float* weights     = (const float*)d_in[6];
    float* out = (float*)d_out;

    jreg_kernel<<<NJ * 3, 256>>>(J_regressor, shapedirs, v_template);
    prep_body_kernel<<<648 + NBODY / 8, dim3(32, 8)>>>(posedirs, shapedirs, v_template, beta, pose);
    smpl_main_kernel<<<dim3(NTILE, NBODY / BN), 128>>>(weights, out);
}

// round 13
// speedup vs baseline: 1.0225x; 1.0225x over previous
#include <cuda_runtime.h>
#include <math.h>

#define NBODY 512
#define NVERT 6890
#define NJ 24
#define NCOL (NVERT*3)
#define KP 224               /* 207 pose + 10 beta + 1 template + 6 zero pad */
#define NTILE 216
#define NCOLPAD (NTILE*96)   /* 20736, col = v*3+c */
#define BN 64
#define BV 32
#define VCHUNK 1723          /* ceil(6890/4) */

typedef unsigned long long ull;

// Scratch (device globals — no allocation anywhere)
__device__ float d_PextT[(size_t)KP * NCOLPAD]; // [k][col], col = v*3+c
__device__ float d_LextT[KP * NBODY];           // [k][body]
__device__ float2 d_Gm2[(NBODY/2) * NJ * 12];   // body-pair interleaved
__device__ float d_Jpart[4 * NJ * 3 * 11];      // 4 v-chunk partials of (Jt|JS)

__constant__ int c_par[NJ] = {0,0,0,0,1,2,3,4,5,6,7,8,9,9,9,12,13,14,16,17,18,19,20,21};

// ---- packed f32x2 helpers -------------------------------------------------
__device__ __forceinline__ ull ffma2(ull a, ull b, ull c) {
    ull d;
    asm("fma.rn.f32x2 %0, %1, %2, %3;" : "=l"(d) : "l"(a), "l"(b), "l"(c));
    return d;
}
__device__ __forceinline__ ull dup2(float x) {
    ull d; unsigned u = __float_as_uint(x);
    asm("mov.b64 %0, {%1, %1};" : "=l"(d) : "r"(u));
    return d;
}
__device__ __forceinline__ float2 unpack2(ull p) {
    float2 r;
    asm("mov.b64 {%0, %1}, %2;" : "=f"(r.x), "=f"(r.y) : "l"(p));
    return r;
}
// ---- cp.async helpers ------------------------------------------------------
__device__ __forceinline__ void cp_async16(unsigned s, const void* g) {
    asm volatile("cp.async.cg.shared.global [%0], [%1], 16;\n" :: "r"(s), "l"(g));
}
__device__ __forceinline__ void cp_commit() {
    asm volatile("cp.async.commit_group;\n");
}
template<int N> __device__ __forceinline__ void cp_wait() {
    asm volatile("cp.async.wait_group %0;\n" :: "n"(N));
}

// ---------------------------------------------------------------------------
// Fused prep, grid 936:
//  blocks [0,648): transpose one 32-col strip over full K=224 (R8 version).
//  blocks [648,936): J_regressor fold partials: 288 = (j,c)*4 v-chunks.
// blockDim = (32,8).
// ---------------------------------------------------------------------------
__global__ void __launch_bounds__(256)
prep_kernel(const float* __restrict__ posedirs,
            const float* __restrict__ shapedirs,
            const float* __restrict__ v_template,
            const float* __restrict__ Jreg)
{
    int bid = blockIdx.x;
    int tx = threadIdx.x, ty = threadIdx.y;
    if (bid < 648) {
        __shared__ float tile[32][229];
        int rbase = bid * 32;
        float r[28];
#pragma unroll
        for (int q = 0; q < 28; q++) {
            int kk0 = (q >> 2) * 32;
            int i = q & 3;
            int row = rbase + ty * 4 + i;
            int k = kk0 + tx;
            float v = 0.f;
            if (row < NCOL) {
                if (k < 207)       v = posedirs[row * 207 + k];
                else if (k < 217)  v = shapedirs[row * 10 + (k - 207)];
                else if (k == 217) v = v_template[row];
            }
            r[q] = v;
        }
#pragma unroll
        for (int q = 0; q < 28; q++) {
            int kk0 = (q >> 2) * 32;
            int i = q & 3;
            tile[ty * 4 + i][kk0 + tx] = r[q];
        }
        __syncthreads();
#pragma unroll
        for (int q = 0; q < 28; q++) {
            int k = q * 8 + ty;
            d_PextT[(size_t)k * NCOLPAD + rbase + tx] = tile[tx][k];
        }
    } else {
        int b2 = bid - 648;
        int part = b2 / 72;          // v-chunk 0..3
        int jc = b2 - part * 72;     // (joint, coord)
        int j = jc / 3, c = jc - j * 3;
        int tid = ty * 32 + tx;
        int vlo = part * VCHUNK;
        int vhi = vlo + VCHUNK; if (vhi > NVERT) vhi = NVERT;
        float acc[11];
#pragma unroll
        for (int q = 0; q < 11; q++) acc[q] = 0.f;
        for (int v = vlo + tid; v < vhi; v += 256) {
            float jr = Jreg[j * NVERT + v];
            acc[0] += jr * v_template[v * 3 + c];
#pragma unroll
            for (int b = 0; b < 10; b++)
                acc[1 + b] += jr * shapedirs[(v * 3 + c) * 10 + b];
        }
        __shared__ float red[8][11];
        int lane = tid & 31, wid = tid >> 5;
#pragma unroll
        for (int q = 0; q < 11; q++) {
            float s = acc[q];
            for (int o = 16; o; o >>= 1) s += __shfl_down_sync(0xffffffffu, s, o);
            if (lane == 0) red[wid][q] = s;
        }
        __syncthreads();
        if (tid < 11) {
            float s = 0.f;
            for (int w = 0; w < 8; w++) s += red[w][tid];
            d_Jpart[part * 792 + jc * 11 + tid] = s;
        }
    }
}

// ---------------------------------------------------------------------------
// Per-body prep: Rodrigues, LextT, joints (from 4 Jpart partials), chain, G'.
// 8 warps/block, 1 warp/body.
// ---------------------------------------------------------------------------
__global__ void __launch_bounds__(256)
body_kernel(const float* __restrict__ beta, const float* __restrict__ pose)
{
    int w = threadIdx.x >> 5;
    int lane = threadIdx.x & 31;
    int n = blockIdx.x * 8 + w;

    __shared__ float sR[8][NJ][9];
    __shared__ float sJ[8][NJ][3];
    __shared__ float sG[8][NJ][12];
    __shared__ float sBeta[8][10];

    if (lane < 10) sBeta[w][lane] = beta[n * 10 + lane];
    if (lane < NJ) {
        float x = pose[n * 72 + lane * 3 + 0];
        float y = pose[n * 72 + lane * 3 + 1];
        float z = pose[n * 72 + lane * 3 + 2];
        float th = sqrtf(x * x + y * y + z * z) + 1e-8f;
        float inv = 1.0f / th;
        x *= inv; y *= inv; z *= inv;
        float s, c;
        sincosf(th, &s, &c);
        float C = 1.0f - c;
        sR[w][lane][0] = c + C * x * x;     sR[w][lane][1] = C * x * y - s * z; sR[w][lane][2] = C * x * z + s * y;
        sR[w][lane][3] = C * x * y + s * z; sR[w][lane][4] = c + C * y * y;     sR[w][lane][5] = C * y * z - s * x;
        sR[w][lane][6] = C * x * z - s * y; sR[w][lane][7] = C * y * z + s * x; sR[w][lane][8] = c + C * z * z;
    }
    __syncwarp();

    for (int t = lane; t < 207; t += 32) {
        int jj = 1 + t / 9, e = t - (t / 9) * 9;
        d_LextT[t * NBODY + n] = sR[w][jj][e] - ((e == 0 || e == 4 || e == 8) ? 1.0f : 0.0f);
    }
    for (int t = lane; t < 17; t += 32) {
        int k = 207 + t;
        d_LextT[k * NBODY + n] = (t < 10) ? sBeta[w][t] : ((k == 217) ? 1.0f : 0.0f);
    }

    for (int t = lane; t < 72; t += 32) {
        int base = t * 11;
        float s = d_Jpart[base] + d_Jpart[792 + base] + d_Jpart[1584 + base] + d_Jpart[2376 + base];
#pragma unroll
        for (int b = 0; b < 10; b++) {
            float coeff = d_Jpart[base + 1 + b] + d_Jpart[792 + base + 1 + b]
                        + d_Jpart[1584 + base + 1 + b] + d_Jpart[2376 + base + 1 + b];
            s += coeff * sBeta[w][b];
        }
        sJ[w][t / 3][t - (t / 3) * 3] = s;
    }
    __syncwarp();

    if (lane < 12) {
        int r = lane >> 2, cc = lane & 3;
        sG[w][0][lane] = (cc < 3) ? sR[w][0][r * 3 + cc] : sJ[w][0][r];
    }
    __syncwarp();
    for (int i = 1; i < NJ; i++) {
        int p = c_par[i];
        float val = 0.f;
        if (lane < 12) {
            int r = lane >> 2, cc = lane & 3;
            float t0, t1, t2;
            if (cc < 3) { t0 = sR[w][i][cc]; t1 = sR[w][i][3 + cc]; t2 = sR[w][i][6 + cc]; }
            else { t0 = sJ[w][i][0] - sJ[w][p][0]; t1 = sJ[w][i][1] - sJ[w][p][1]; t2 = sJ[w][i][2] - sJ[w][p][2]; }
            val = sG[w][p][r * 4 + 0] * t0 + sG[w][p][r * 4 + 1] * t1 + sG[w][p][r * 4 + 2] * t2;
            if (cc == 3) val += sG[w][p][r * 4 + 3];
        }
        __syncwarp();
        if (lane < 12) sG[w][i][lane] = val;
        __syncwarp();
    }

    for (int t = lane; t < 72; t += 32) {
        int jj = t / 3, r = t - jj * 3;
        float rj = sG[w][jj][r * 4 + 0] * sJ[w][jj][0] + sG[w][jj][r * 4 + 1] * sJ[w][jj][1]
                 + sG[w][jj][r * 4 + 2] * sJ[w][jj][2];
        sG[w][jj][r * 4 + 3] -= rj;
    }
    __syncwarp();
    for (int t = lane; t < NJ * 12; t += 32) {
        float g = sG[w][t / 12][t - (t / 12) * 12];
        if (n & 1) d_Gm2[(n >> 1) * (NJ * 12) + t].y = g;
        else       d_Gm2[(n >> 1) * (NJ * 12) + t].x = g;
    }
}

// ---------------------------------------------------------------------------
// Main fused kernel — EXACT R8 shape (best passing: 179.3us total).
// 128 thr = 16 tx x 8 ty. Tile 64 bodies x 32 verts.
// ---------------------------------------------------------------------------
#define AS_OFF(buf, kk, c) ((buf) * 2048 + (kk) * 64 + (c))
#define BS_OFF(buf, kk, c) (4096 + (buf) * 3200 + (kk) * 100 + (c))
#define GS_STRIDE 74
#define GBUF_F2 2368
#define WS_OFF 9472

__global__ void __launch_bounds__(128, 4)
smpl_main_kernel(const float* __restrict__ weights, float* __restrict__ out)
{
    __shared__ __align__(16) float smemf[10496];   // 42 KB

    float2* Gs2 = (float2*)smemf;
    float* Ws = smemf + WS_OFF;

    int tid = threadIdx.x;
    int tx = tid & 15, ty = tid >> 4;
    int nBase = blockIdx.y * BN;
    int vBase = blockIdx.x * BV;
    int colBase = blockIdx.x * 96;
    int pBase = nBase >> 1;

    unsigned smem_base = (unsigned)__cvta_generic_to_shared(smemf);

    ull vp2[4][6];
#pragma unroll
    for (int p = 0; p < 4; p++)
#pragma unroll
        for (int j = 0; j < 6; j++) vp2[p][j] = 0ull;

    {
#pragma unroll
        for (int t = 0; t < 4; t++) {
            int idx = tid + t * 128;
            int kk = idx >> 4, c4 = idx & 15;
            cp_async16(smem_base + AS_OFF(0, kk, c4 * 4) * 4,
                       &d_LextT[kk * NBODY + nBase + c4 * 4]);
        }
#pragma unroll
        for (int t = 0; t < 6; t++) {
            int idx = tid + t * 128;
            int kk = idx / 24, c4 = idx - kk * 24;
            cp_async16(smem_base + BS_OFF(0, kk, c4 * 4) * 4,
                       &d_PextT[(size_t)kk * NCOLPAD + colBase + c4 * 4]);
        }
        cp_commit();
    }

    for (int tt = 0; tt < 7; tt++) {
        int cur = tt & 1;
        if (tt < 6) {
            int nb = cur ^ 1;
            int k1 = (tt + 1) * 32;
#pragma unroll
            for (int t = 0; t < 4; t++) {
                int idx = tid + t * 128;
                int kk = idx >> 4, c4 = idx & 15;
                cp_async16(smem_base + AS_OFF(nb, kk, c4 * 4) * 4,
                           &d_LextT[(k1 + kk) * NBODY + nBase + c4 * 4]);
            }
#pragma unroll
            for (int t = 0; t < 6; t++) {
                int idx = tid + t * 128;
                int kk = idx / 24, c4 = idx - kk * 24;
                cp_async16(smem_base + BS_OFF(nb, kk, c4 * 4) * 4,
                           &d_PextT[(size_t)(k1 + kk) * NCOLPAD + colBase + c4 * 4]);
            }
            cp_commit();
            cp_wait<1>();
        } else {
            cp_wait<0>();
        }
        __syncthreads();

#pragma unroll
        for (int kk = 0; kk < 32; kk++) {
            ulonglong2 A0 = *(const ulonglong2*)&smemf[AS_OFF(cur, kk, ty * 8)];
            ulonglong2 A1 = *(const ulonglong2*)&smemf[AS_OFF(cur, kk, ty * 8 + 4)];
            float2 b01 = *(const float2*)&smemf[BS_OFF(cur, kk, tx * 6)];
            float2 b23 = *(const float2*)&smemf[BS_OFF(cur, kk, tx * 6 + 2)];
            float2 b45 = *(const float2*)&smemf[BS_OFF(cur, kk, tx * 6 + 4)];
            ull bd[6];
            bd[0] = dup2(b01.x); bd[1] = dup2(b01.y);
            bd[2] = dup2(b23.x); bd[3] = dup2(b23.y);
            bd[4] = dup2(b45.x); bd[5] = dup2(b45.y);
#pragma unroll
            for (int j = 0; j < 6; j++) {
                vp2[0][j] = ffma2(A0.x, bd[j], vp2[0][j]);
                vp2[1][j] = ffma2(A0.y, bd[j], vp2[1][j]);
                vp2[2][j] = ffma2(A1.x, bd[j], vp2[2][j]);
                vp2[3][j] = ffma2(A1.y, bd[j], vp2[3][j]);
            }
        }
        __syncthreads();
    }

    // ---- Phase 2 prologue: prefetch G chunk 0, load Ws ----
    {
#pragma unroll
        for (int i = 0; i < 9; i++) {
            int t = tid + i * 128;
            int pl = t / 36, seg = t - pl * 36;
            cp_async16(smem_base + (pl * GS_STRIDE + seg * 2) * 8,
                       &d_Gm2[(pBase + pl) * (NJ * 12) + seg * 2]);
        }
        cp_commit();
    }
    for (int t = tid; t < BV * 24; t += 128) {
        int vl = t / 24, j2 = t - vl * 24;
        int v = vBase + vl;
        Ws[vl * 25 + j2] = (v < NVERT) ? weights[v * 24 + j2] : 0.f;
    }

    ull o2[4][6];
#pragma unroll
    for (int p = 0; p < 4; p++)
#pragma unroll
        for (int j = 0; j < 6; j++) o2[p][j] = 0ull;

    for (int jc = 0; jc < 4; jc++) {
        int cur = jc & 1;
        if (jc < 3) {
            int nb = cur ^ 1;
#pragma unroll
            for (int i = 0; i < 9; i++) {
                int t = tid + i * 128;
                int pl = t / 36, seg = t - pl * 36;
                cp_async16(smem_base + (nb * GBUF_F2 + pl * GS_STRIDE + seg * 2) * 8,
                           &d_Gm2[(pBase + pl) * (NJ * 12) + (jc + 1) * 72 + seg * 2]);
            }
            cp_commit();
            cp_wait<1>();
        } else {
            cp_wait<0>();
        }
        __syncthreads();
#pragma unroll
        for (int jj = 0; jj < 6; jj++) {
            ull w0 = dup2(Ws[(tx * 2) * 25 + jc * 6 + jj]);
            ull w1 = dup2(Ws[(tx * 2 + 1) * 25 + jc * 6 + jj]);
#pragma unroll
            for (int q = 0; q < 4; q++) {
                const ull* g = (const ull*)&Gs2[cur * GBUF_F2 + (ty * 4 + q) * GS_STRIDE + jj * 12];
#pragma unroll
                for (int c = 0; c < 3; c++) {
                    ull g0 = g[c * 4 + 0], g1 = g[c * 4 + 1];
                    ull g2 = g[c * 4 + 2], g3 = g[c * 4 + 3];
                    ull t0 = ffma2(g0, vp2[q][0], ffma2(g1, vp2[q][1], ffma2(g2, vp2[q][2], g3)));
                    o2[q][c] = ffma2(w0, t0, o2[q][c]);
                    ull t1 = ffma2(g0, vp2[q][3], ffma2(g1, vp2[q][4], ffma2(g2, vp2[q][5], g3)));
                    o2[q][3 + c] = ffma2(w1, t1, o2[q][3 + c]);
                }
            }
        }
        __syncthreads();
    }

    // ---- Store ----
#pragma unroll
    for (int q = 0; q < 4; q++) {
        int n0 = nBase + ty * 8 + 2 * q;
#pragma unroll
        for (int vv = 0; vv < 2; vv++) {
            int v = vBase + tx * 2 + vv;
            if (v < NVERT) {
                size_t b0 = ((size_t)n0 * NVERT + v) * 3;
                size_t b1 = ((size_t)(n0 + 1) * NVERT + v) * 3;
#pragma unroll
                for (int c = 0; c < 3; c++) {
                    float2 pr = unpack2(o2[q][vv * 3 + c]);
                    out[b0 + c] = pr.x;
                    out[b1 + c] = pr.y;
                }
            }
        }
    }
}

// ---------------------------------------------------------------------------
extern "C" void kernel_launch(void* const* d_in, const int* in_sizes, int n_in,
                              void* d_out, int out_size)
{
    const float* beta        = (const float*)d_in[0];
    const float* pose        = (const float*)d_in[1];
    const float* v_template  = (const float*)d_in[2];
    const float* shapedirs   = (const float*)d_in[3];
    const float* posedirs    = (const float*)d_in[4];
    const float* J_regressor = (const float*)d_in[5];
    const float* weights     = (const float*)d_in[6];
    float* out = (float*)d_out;

    prep_kernel<<<936, dim3(32, 8)>>>(posedirs, shapedirs, v_template, J_regressor);
    body_kernel<<<NBODY / 8, 256>>>(beta, pose);
    smpl_main_kernel<<<dim3(NTILE, NBODY / BN), 128>>>(weights, out);
}

// round 14
// speedup vs baseline: 1.0726x; 1.0490x over previous
#include <cuda_runtime.h>
#include <math.h>

#define NBODY 512
#define NVERT 6890
#define NJ 24
#define NCOL (NVERT*3)
#define KP 224               /* 207 pose + 10 beta + 1 template + 6 zero pad */
#define NTILE 216
#define NCOLPAD (NTILE*96)   /* 20736, col = v*3+c */
#define BN 64
#define BV 32
#define VCHUNK 1723          /* ceil(6890/4) */

typedef unsigned long long ull;

// Scratch (device globals — no allocation anywhere)
__device__ float d_PextT[(size_t)KP * NCOLPAD]; // [k][col], col = v*3+c
__device__ float d_LextT[KP * NBODY];           // [k][body]
__device__ float2 d_Gm2[(NBODY/2) * NJ * 12];   // body-pair interleaved
__device__ float d_Jpart[4 * NJ * 3 * 11];      // 4 v-chunk partials of (Jt|JS)

__constant__ int c_par[NJ] = {0,0,0,0,1,2,3,4,5,6,7,8,9,9,9,12,13,14,16,17,18,19,20,21};

// ---- packed f32x2 helpers -------------------------------------------------
__device__ __forceinline__ ull ffma2(ull a, ull b, ull c) {
    ull d;
    asm("fma.rn.f32x2 %0, %1, %2, %3;" : "=l"(d) : "l"(a), "l"(b), "l"(c));
    return d;
}
__device__ __forceinline__ ull dup2(float x) {
    ull d; unsigned u = __float_as_uint(x);
    asm("mov.b64 %0, {%1, %1};" : "=l"(d) : "r"(u));
    return d;
}
__device__ __forceinline__ float2 unpack2(ull p) {
    float2 r;
    asm("mov.b64 {%0, %1}, %2;" : "=f"(r.x), "=f"(r.y) : "l"(p));
    return r;
}
// ---- cp.async helpers ------------------------------------------------------
__device__ __forceinline__ void cp_async16(unsigned s, const void* g) {
    asm volatile("cp.async.cg.shared.global [%0], [%1], 16;\n" :: "r"(s), "l"(g));
}
__device__ __forceinline__ void cp_commit() {
    asm volatile("cp.async.commit_group;\n");
}
template<int N> __device__ __forceinline__ void cp_wait() {
    asm volatile("cp.async.wait_group %0;\n" :: "n"(N));
}

// ---------------------------------------------------------------------------
// Fused prep, grid 936 (unchanged from R12):
//  blocks [0,648): transpose one 32-col strip over full K=224.
//  blocks [648,936): J_regressor fold partials: 288 = (j,c)*4 v-chunks.
// blockDim = (32,8).
// ---------------------------------------------------------------------------
__global__ void __launch_bounds__(256)
prep_kernel(const float* __restrict__ posedirs,
            const float* __restrict__ shapedirs,
            const float* __restrict__ v_template,
            const float* __restrict__ Jreg)
{
    int bid = blockIdx.x;
    int tx = threadIdx.x, ty = threadIdx.y;
    if (bid < 648) {
        __shared__ float tile[32][229];
        int rbase = bid * 32;
        float r[28];
#pragma unroll
        for (int q = 0; q < 28; q++) {
            int kk0 = (q >> 2) * 32;
            int i = q & 3;
            int row = rbase + ty * 4 + i;
            int k = kk0 + tx;
            float v = 0.f;
            if (row < NCOL) {
                if (k < 207)       v = posedirs[row * 207 + k];
                else if (k < 217)  v = shapedirs[row * 10 + (k - 207)];
                else if (k == 217) v = v_template[row];
            }
            r[q] = v;
        }
#pragma unroll
        for (int q = 0; q < 28; q++) {
            int kk0 = (q >> 2) * 32;
            int i = q & 3;
            tile[ty * 4 + i][kk0 + tx] = r[q];
        }
        __syncthreads();
#pragma unroll
        for (int q = 0; q < 28; q++) {
            int k = q * 8 + ty;
            d_PextT[(size_t)k * NCOLPAD + rbase + tx] = tile[tx][k];
        }
    } else {
        int b2 = bid - 648;
        int part = b2 / 72;          // v-chunk 0..3
        int jc = b2 - part * 72;     // (joint, coord)
        int j = jc / 3, c = jc - j * 3;
        int tid = ty * 32 + tx;
        int vlo = part * VCHUNK;
        int vhi = vlo + VCHUNK; if (vhi > NVERT) vhi = NVERT;
        float acc[11];
#pragma unroll
        for (int q = 0; q < 11; q++) acc[q] = 0.f;
        for (int v = vlo + tid; v < vhi; v += 256) {
            float jr = Jreg[j * NVERT + v];
            acc[0] += jr * v_template[v * 3 + c];
#pragma unroll
            for (int b = 0; b < 10; b++)
                acc[1 + b] += jr * shapedirs[(v * 3 + c) * 10 + b];
        }
        __shared__ float red[8][11];
        int lane = tid & 31, wid = tid >> 5;
#pragma unroll
        for (int q = 0; q < 11; q++) {
            float s = acc[q];
            for (int o = 16; o; o >>= 1) s += __shfl_down_sync(0xffffffffu, s, o);
            if (lane == 0) red[wid][q] = s;
        }
        __syncthreads();
        if (tid < 11) {
            float s = 0.f;
            for (int w = 0; w < 8; w++) s += red[w][tid];
            d_Jpart[part * 792 + jc * 11 + tid] = s;
        }
    }
}

// ---------------------------------------------------------------------------
// Per-body prep (unchanged from R12). 8 warps/block, 1 warp/body.
// ---------------------------------------------------------------------------
__global__ void __launch_bounds__(256)
body_kernel(const float* __restrict__ beta, const float* __restrict__ pose)
{
    int w = threadIdx.x >> 5;
    int lane = threadIdx.x & 31;
    int n = blockIdx.x * 8 + w;

    __shared__ float sR[8][NJ][9];
    __shared__ float sJ[8][NJ][3];
    __shared__ float sG[8][NJ][12];
    __shared__ float sBeta[8][10];

    if (lane < 10) sBeta[w][lane] = beta[n * 10 + lane];
    if (lane < NJ) {
        float x = pose[n * 72 + lane * 3 + 0];
        float y = pose[n * 72 + lane * 3 + 1];
        float z = pose[n * 72 + lane * 3 + 2];
        float th = sqrtf(x * x + y * y + z * z) + 1e-8f;
        float inv = 1.0f / th;
        x *= inv; y *= inv; z *= inv;
        float s, c;
        sincosf(th, &s, &c);
        float C = 1.0f - c;
        sR[w][lane][0] = c + C * x * x;     sR[w][lane][1] = C * x * y - s * z; sR[w][lane][2] = C * x * z + s * y;
        sR[w][lane][3] = C * x * y + s * z; sR[w][lane][4] = c + C * y * y;     sR[w][lane][5] = C * y * z - s * x;
        sR[w][lane][6] = C * x * z - s * y; sR[w][lane][7] = C * y * z + s * x; sR[w][lane][8] = c + C * z * z;
    }
    __syncwarp();

    for (int t = lane; t < 207; t += 32) {
        int jj = 1 + t / 9, e = t - (t / 9) * 9;
        d_LextT[t * NBODY + n] = sR[w][jj][e] - ((e == 0 || e == 4 || e == 8) ? 1.0f : 0.0f);
    }
    for (int t = lane; t < 17; t += 32) {
        int k = 207 + t;
        d_LextT[k * NBODY + n] = (t < 10) ? sBeta[w][t] : ((k == 217) ? 1.0f : 0.0f);
    }

    for (int t = lane; t < 72; t += 32) {
        int base = t * 11;
        float s = d_Jpart[base] + d_Jpart[792 + base] + d_Jpart[1584 + base] + d_Jpart[2376 + base];
#pragma unroll
        for (int b = 0; b < 10; b++) {
            float coeff = d_Jpart[base + 1 + b] + d_Jpart[792 + base + 1 + b]
                        + d_Jpart[1584 + base + 1 + b] + d_Jpart[2376 + base + 1 + b];
            s += coeff * sBeta[w][b];
        }
        sJ[w][t / 3][t - (t / 3) * 3] = s;
    }
    __syncwarp();

    if (lane < 12) {
        int r = lane >> 2, cc = lane & 3;
        sG[w][0][lane] = (cc < 3) ? sR[w][0][r * 3 + cc] : sJ[w][0][r];
    }
    __syncwarp();
    for (int i = 1; i < NJ; i++) {
        int p = c_par[i];
        float val = 0.f;
        if (lane < 12) {
            int r = lane >> 2, cc = lane & 3;
            float t0, t1, t2;
            if (cc < 3) { t0 = sR[w][i][cc]; t1 = sR[w][i][3 + cc]; t2 = sR[w][i][6 + cc]; }
            else { t0 = sJ[w][i][0] - sJ[w][p][0]; t1 = sJ[w][i][1] - sJ[w][p][1]; t2 = sJ[w][i][2] - sJ[w][p][2]; }
            val = sG[w][p][r * 4 + 0] * t0 + sG[w][p][r * 4 + 1] * t1 + sG[w][p][r * 4 + 2] * t2;
            if (cc == 3) val += sG[w][p][r * 4 + 3];
        }
        __syncwarp();
        if (lane < 12) sG[w][i][lane] = val;
        __syncwarp();
    }

    for (int t = lane; t < 72; t += 32) {
        int jj = t / 3, r = t - jj * 3;
        float rj = sG[w][jj][r * 4 + 0] * sJ[w][jj][0] + sG[w][jj][r * 4 + 1] * sJ[w][jj][1]
                 + sG[w][jj][r * 4 + 2] * sJ[w][jj][2];
        sG[w][jj][r * 4 + 3] -= rj;
    }
    __syncwarp();
    for (int t = lane; t < NJ * 12; t += 32) {
        float g = sG[w][t / 12][t - (t / 12) * 12];
        if (n & 1) d_Gm2[(n >> 1) * (NJ * 12) + t].y = g;
        else       d_Gm2[(n >> 1) * (NJ * 12) + t].x = g;
    }
}

// ---------------------------------------------------------------------------
// Main fused kernel. 128 thr = 16 tx x 8 ty. Tile 64 bodies x 32 verts.
// Phases 1-2 identical to R12; NEW: smem-staged coalesced float2 epilogue.
// ---------------------------------------------------------------------------
#define AS_OFF(buf, kk, c) ((buf) * 2048 + (kk) * 64 + (c))
#define BS_OFF(buf, kk, c) (4096 + (buf) * 3200 + (kk) * 100 + (c))
#define GS_STRIDE 74
#define GBUF_F2 2368
#define WS_OFF 9472
#define SO_STRIDE 98   /* floats per body row in staging tile */

__global__ void __launch_bounds__(128, 4)
smpl_main_kernel(const float* __restrict__ weights, float* __restrict__ out)
{
    __shared__ __align__(16) float smemf[10496];   // 42 KB

    float2* Gs2 = (float2*)smemf;
    float* Ws = smemf + WS_OFF;

    int tid = threadIdx.x;
    int tx = tid & 15, ty = tid >> 4;
    int nBase = blockIdx.y * BN;
    int vBase = blockIdx.x * BV;
    int colBase = blockIdx.x * 96;
    int pBase = nBase >> 1;

    unsigned smem_base = (unsigned)__cvta_generic_to_shared(smemf);

    ull vp2[4][6];
#pragma unroll
    for (int p = 0; p < 4; p++)
#pragma unroll
        for (int j = 0; j < 6; j++) vp2[p][j] = 0ull;

    {
#pragma unroll
        for (int t = 0; t < 4; t++) {
            int idx = tid + t * 128;
            int kk = idx >> 4, c4 = idx & 15;
            cp_async16(smem_base + AS_OFF(0, kk, c4 * 4) * 4,
                       &d_LextT[kk * NBODY + nBase + c4 * 4]);
        }
#pragma unroll
        for (int t = 0; t < 6; t++) {
            int idx = tid + t * 128;
            int kk = idx / 24, c4 = idx - kk * 24;
            cp_async16(smem_base + BS_OFF(0, kk, c4 * 4) * 4,
                       &d_PextT[(size_t)kk * NCOLPAD + colBase + c4 * 4]);
        }
        cp_commit();
    }

    for (int tt = 0; tt < 7; tt++) {
        int cur = tt & 1;
        if (tt < 6) {
            int nb = cur ^ 1;
            int k1 = (tt + 1) * 32;
#pragma unroll
            for (int t = 0; t < 4; t++) {
                int idx = tid + t * 128;
                int kk = idx >> 4, c4 = idx & 15;
                cp_async16(smem_base + AS_OFF(nb, kk, c4 * 4) * 4,
                           &d_LextT[(k1 + kk) * NBODY + nBase + c4 * 4]);
            }
#pragma unroll
            for (int t = 0; t < 6; t++) {
                int idx = tid + t * 128;
                int kk = idx / 24, c4 = idx - kk * 24;
                cp_async16(smem_base + BS_OFF(nb, kk, c4 * 4) * 4,
                           &d_PextT[(size_t)(k1 + kk) * NCOLPAD + colBase + c4 * 4]);
            }
            cp_commit();
            cp_wait<1>();
        } else {
            cp_wait<0>();
        }
        __syncthreads();

#pragma unroll
        for (int kk = 0; kk < 32; kk++) {
            ulonglong2 A0 = *(const ulonglong2*)&smemf[AS_OFF(cur, kk, ty * 8)];
            ulonglong2 A1 = *(const ulonglong2*)&smemf[AS_OFF(cur, kk, ty * 8 + 4)];
            float2 b01 = *(const float2*)&smemf[BS_OFF(cur, kk, tx * 6)];
            float2 b23 = *(const float2*)&smemf[BS_OFF(cur, kk, tx * 6 + 2)];
            float2 b45 = *(const float2*)&smemf[BS_OFF(cur, kk, tx * 6 + 4)];
            ull bd[6];
            bd[0] = dup2(b01.x); bd[1] = dup2(b01.y);
            bd[2] = dup2(b23.x); bd[3] = dup2(b23.y);
            bd[4] = dup2(b45.x); bd[5] = dup2(b45.y);
#pragma unroll
            for (int j = 0; j < 6; j++) {
                vp2[0][j] = ffma2(A0.x, bd[j], vp2[0][j]);
                vp2[1][j] = ffma2(A0.y, bd[j], vp2[1][j]);
                vp2[2][j] = ffma2(A1.x, bd[j], vp2[2][j]);
                vp2[3][j] = ffma2(A1.y, bd[j], vp2[3][j]);
            }
        }
        __syncthreads();
    }

    // ---- Phase 2 prologue: prefetch G chunk 0, load Ws ----
    {
#pragma unroll
        for (int i = 0; i < 9; i++) {
            int t = tid + i * 128;
            int pl = t / 36, seg = t - pl * 36;
            cp_async16(smem_base + (pl * GS_STRIDE + seg * 2) * 8,
                       &d_Gm2[(pBase + pl) * (NJ * 12) + seg * 2]);
        }
        cp_commit();
    }
    for (int t = tid; t < BV * 24; t += 128) {
        int vl = t / 24, j2 = t - vl * 24;
        int v = vBase + vl;
        Ws[vl * 25 + j2] = (v < NVERT) ? weights[v * 24 + j2] : 0.f;
    }

    ull o2[4][6];
#pragma unroll
    for (int p = 0; p < 4; p++)
#pragma unroll
        for (int j = 0; j < 6; j++) o2[p][j] = 0ull;

    for (int jc = 0; jc < 4; jc++) {
        int cur = jc & 1;
        if (jc < 3) {
            int nb = cur ^ 1;
#pragma unroll
            for (int i = 0; i < 9; i++) {
                int t = tid + i * 128;
                int pl = t / 36, seg = t - pl * 36;
                cp_async16(smem_base + (nb * GBUF_F2 + pl * GS_STRIDE + seg * 2) * 8,
                           &d_Gm2[(pBase + pl) * (NJ * 12) + (jc + 1) * 72 + seg * 2]);
            }
            cp_commit();
            cp_wait<1>();
        } else {
            cp_wait<0>();
        }
        __syncthreads();
#pragma unroll
        for (int jj = 0; jj < 6; jj++) {
            ull w0 = dup2(Ws[(tx * 2) * 25 + jc * 6 + jj]);
            ull w1 = dup2(Ws[(tx * 2 + 1) * 25 + jc * 6 + jj]);
#pragma unroll
            for (int q = 0; q < 4; q++) {
                const ull* g = (const ull*)&Gs2[cur * GBUF_F2 + (ty * 4 + q) * GS_STRIDE + jj * 12];
#pragma unroll
                for (int c = 0; c < 3; c++) {
                    ull g0 = g[c * 4 + 0], g1 = g[c * 4 + 1];
                    ull g2 = g[c * 4 + 2], g3 = g[c * 4 + 3];
                    ull t0 = ffma2(g0, vp2[q][0], ffma2(g1, vp2[q][1], ffma2(g2, vp2[q][2], g3)));
                    o2[q][c] = ffma2(w0, t0, o2[q][c]);
                    ull t1 = ffma2(g0, vp2[q][3], ffma2(g1, vp2[q][4], ffma2(g2, vp2[q][5], g3)));
                    o2[q][3 + c] = ffma2(w1, t1, o2[q][3 + c]);
                }
            }
        }
        __syncthreads();
    }

    // ---- Epilogue: stage in smem, then coalesced float2 stores ----
    {
        float* So = smemf;   // [64][SO_STRIDE]
#pragma unroll
        for (int q = 0; q < 4; q++) {
#pragma unroll
            for (int vv = 0; vv < 2; vv++) {
#pragma unroll
                for (int c = 0; c < 3; c++) {
                    float2 pr = unpack2(o2[q][vv * 3 + c]);
                    int col = (tx * 2 + vv) * 3 + c;
                    So[(ty * 8 + 2 * q) * SO_STRIDE + col] = pr.x;
                    So[(ty * 8 + 2 * q + 1) * SO_STRIDE + col] = pr.y;
                }
            }
        }
        __syncthreads();
        int colBase2 = colBase >> 1;   // float2 units
#pragma unroll
        for (int i = 0; i < 24; i++) {
            int t = tid + i * 128;
            int nl = t / 48, c2 = t - nl * 48;
            if (colBase2 + c2 < (NVERT * 3) / 2) {
                *(float2*)&out[(size_t)(nBase + nl) * (NVERT * 3) + colBase + c2 * 2] =
                    *(const float2*)&So[nl * SO_STRIDE + c2 * 2];
            }
        }
    }
}

// ---------------------------------------------------------------------------
extern "C" void kernel_launch(void* const* d_in, const int* in_sizes, int n_in,
                              void* d_out, int out_size)
{
    const float* beta        = (const float*)d_in[0];
    const float* pose        = (const float*)d_in[1];
    const float* v_template  = (const float*)d_in[2];
    const float* shapedirs   = (const float*)d_in[3];
    const float* posedirs    = (const float*)d_in[4];
    const float* J_regressor = (const float*)d_in[5];
    const float* weights     = (const float*)d_in[6];
    float* out = (float*)d_out;

    prep_kernel<<<936, dim3(32, 8)>>>(posedirs, shapedirs, v_template, J_regressor);
    body_kernel<<<NBODY / 8, 256>>>(beta, pose);
    smpl_main_kernel<<<dim3(NTILE, NBODY / BN), 128>>>(weights, out);
}